// round 8
// baseline (speedup 1.0000x reference)
#include <cuda_runtime.h>

#define B_  4
#define K_  16
#define H_  480
#define W_  640
#define HW_ (H_*W_)
#define P_  200000

// Truncation threshold. Measured at 1e-3 (R7): rel_err = 4.80e-4 (gate 1e-3).
#define EPS_T 1e-3f

// Pre-packed point-cloud features: one aligned 16B row per point -> one 32B
// L2 sector per gather.
__device__ float4 g_tab[P_];

__global__ void prep_kernel(const float* __restrict__ pt) {
    int i = blockIdx.x * blockDim.x + threadIdx.x;
    if (i < P_) {
        g_tab[i] = make_float4(pt[i], pt[P_ + i], pt[2 * P_ + i], 0.f);
    }
}

__global__ void __launch_bounds__(256) composite_kernel(
    const int*   __restrict__ frag,   // int32 (JAX demotes int64 without x64 mode)
    const float* __restrict__ alpha,
    const float* __restrict__ im,
    float*       __restrict__ out)
{
    int p    = blockIdx.x * blockDim.x + threadIdx.x;  // pixel within a batch image
    int b    = blockIdx.y;
    int quad = (threadIdx.x >> 3) & 3;                 // lane quadrant (lane>>3)
    size_t base = (size_t)b * K_ * HW_ + p;

    float T  = 1.f;
    float c0 = 0.f, c1 = 0.f, c2 = 0.f;
    bool  bg = false;

    #pragma unroll
    for (int half = 0; half < 2; half++) {
        // Batch-load 8 frags + 8 alphas (16 independent LDGs -> full MLP).
        int   f[8];
        float w[8];
        #pragma unroll
        for (int j = 0; j < 8; j++) {
            size_t off = base + (size_t)(half * 8 + j) * HW_;
            f[j] = frag[off];
            w[j] = alpha[off];
        }
        if (half == 0) {
            bg = (f[0] < 0);
            if (bg) T = 0.f;   // background: zero every weight -> zero gathers
        }

        // Weight chain in pure FMA; data-predicated truncation.
        #pragma unroll
        for (int j = 0; j < 8; j++) {
            bool  v  = (f[j] >= 0);
            float av = v ? w[j] : 0.f;
            w[j] = (v && T > EPS_T) ? av * T : 0.f;   // exclusive-transmittance weight
            T *= (1.f - av);
        }

        // Gather phase, quadrant-split: each LDG instruction has <= 8 active
        // lanes -> <= 8 divergent lines, shifting L1tex wavefronts from the
        // 2.07 cyc within-LDG replay regime toward the 1.0 cyc cross-LDG rate.
        #pragma unroll
        for (int q = 0; q < 4; q++) {
            if (quad == q) {
                #pragma unroll
                for (int j = 0; j < 8; j++) {
                    if (w[j] != 0.f) {
                        float4 ft = __ldg(&g_tab[f[j]]);
                        c0 = fmaf(w[j], ft.x, c0);
                        c1 = fmaf(w[j], ft.y, c1);
                        c2 = fmaf(w[j], ft.z, c2);
                    }
                }
            }
        }
    }

    size_t ob = (size_t)b * 3 * HW_ + p;
    out[ob          ] = bg ? im[p          ] : c0;
    out[ob +     HW_] = bg ? im[p +     HW_] : c1;
    out[ob + 2 * HW_] = bg ? im[p + 2 * HW_] : c2;
}

extern "C" void kernel_launch(void* const* d_in, const int* in_sizes, int n_in,
                              void* d_out, int out_size) {
    const int*   frag  = (const int*)  d_in[0];
    const float* alpha = (const float*)d_in[1];
    const float* pt    = (const float*)d_in[2];
    const float* im    = (const float*)d_in[3];
    float*       out   = (float*)      d_out;

    prep_kernel<<<(P_ + 255) / 256, 256>>>(pt);

    dim3 grid(HW_ / 256, B_);   // 1200 x 4 blocks
    composite_kernel<<<grid, 256>>>(frag, alpha, im, out);
}

// round 9
// speedup vs baseline: 1.0030x; 1.0030x over previous
#include <cuda_runtime.h>

#define B_  4
#define K_  16
#define H_  480
#define W_  640
#define HW_ (H_*W_)
#define P_  200000

// Truncation threshold. Measured at 1e-3 (R7): rel_err = 4.80e-4 (gate 1e-3).
#define EPS_T 1e-3f

// Pre-packed point-cloud features: one aligned 16B row per point -> one 32B
// L2 sector per gather.
__device__ float4 g_tab[P_];

__global__ void prep_kernel(const float* __restrict__ pt) {
    int i = blockIdx.x * blockDim.x + threadIdx.x;
    if (i < P_) {
        g_tab[i] = make_float4(pt[i], pt[P_ + i], pt[2 * P_ + i], 0.f);
    }
}

__global__ void __launch_bounds__(256) composite_kernel(
    const int*   __restrict__ frag,   // int32 (JAX demotes int64 without x64 mode)
    const float* __restrict__ alpha,
    const float* __restrict__ im,
    float*       __restrict__ out)
{
    int p    = blockIdx.x * blockDim.x + threadIdx.x;  // pixel within a batch image
    int b    = blockIdx.y;
    int quad = (threadIdx.x >> 3) & 3;                 // lane quadrant (lane>>3)
    size_t base = (size_t)b * K_ * HW_ + p;

    float T  = 1.f;
    float c0 = 0.f, c1 = 0.f, c2 = 0.f;
    bool  bg = false;

    #pragma unroll
    for (int half = 0; half < 2; half++) {
        // Batch-load 8 frags + 8 alphas (16 independent LDGs -> full MLP).
        int   f[8];
        float w[8];
        #pragma unroll
        for (int j = 0; j < 8; j++) {
            size_t off = base + (size_t)(half * 8 + j) * HW_;
            f[j] = frag[off];
            w[j] = alpha[off];
        }
        if (half == 0) {
            bg = (f[0] < 0);
            if (bg) T = 0.f;   // background: zero every weight -> zero gathers
        }

        // Weight chain in pure FMA; data-predicated truncation.
        #pragma unroll
        for (int j = 0; j < 8; j++) {
            bool  v  = (f[j] >= 0);
            float av = v ? w[j] : 0.f;
            w[j] = (v && T > EPS_T) ? av * T : 0.f;   // exclusive-transmittance weight
            T *= (1.f - av);
        }

        // Gather phase, quadrant-split: each LDG instruction has <= 8 active
        // lanes -> <= 8 divergent lines, shifting L1tex wavefronts from the
        // 2.07 cyc within-LDG replay regime toward the 1.0 cyc cross-LDG rate.
        #pragma unroll
        for (int q = 0; q < 4; q++) {
            if (quad == q) {
                #pragma unroll
                for (int j = 0; j < 8; j++) {
                    if (w[j] != 0.f) {
                        float4 ft = __ldg(&g_tab[f[j]]);
                        c0 = fmaf(w[j], ft.x, c0);
                        c1 = fmaf(w[j], ft.y, c1);
                        c2 = fmaf(w[j], ft.z, c2);
                    }
                }
            }
        }
    }

    size_t ob = (size_t)b * 3 * HW_ + p;
    out[ob          ] = bg ? im[p          ] : c0;
    out[ob +     HW_] = bg ? im[p +     HW_] : c1;
    out[ob + 2 * HW_] = bg ? im[p + 2 * HW_] : c2;
}

extern "C" void kernel_launch(void* const* d_in, const int* in_sizes, int n_in,
                              void* d_out, int out_size) {
    const int*   frag  = (const int*)  d_in[0];
    const float* alpha = (const float*)d_in[1];
    const float* pt    = (const float*)d_in[2];
    const float* im    = (const float*)d_in[3];
    float*       out   = (float*)      d_out;

    prep_kernel<<<(P_ + 255) / 256, 256>>>(pt);

    dim3 grid(HW_ / 256, B_);   // 1200 x 4 blocks
    composite_kernel<<<grid, 256>>>(frag, alpha, im, out);
}

// round 10
// speedup vs baseline: 1.3677x; 1.3636x over previous
#include <cuda_runtime.h>

#define B_  4
#define K_  16
#define H_  480
#define W_  640
#define HW_ (H_*W_)
#define P_  200000

// Truncation threshold. Measured (R7/R8): rel_err = 4.80e-4 at 1e-3 (gate 1e-3).
#define EPS_T 1e-3f

// Pre-packed point-cloud features: one aligned 16B row per point -> one 32B
// L2 sector per gather.
__device__ float4 g_tab[P_];

__global__ void prep_kernel(const float* __restrict__ pt) {
    int i = blockIdx.x * blockDim.x + threadIdx.x;
    if (i < P_) {
        g_tab[i] = make_float4(pt[i], pt[P_ + i], pt[2 * P_ + i], 0.f);
    }
}

// Exact R6 structure (the proven-fastest shape); only EPS and the occupancy
// cap changed. __launch_bounds__(256, 8) pins regs <= 32 -> 8 blocks/SM.
__global__ void __launch_bounds__(256, 8) composite_kernel(
    const int*   __restrict__ frag,   // int32 (JAX demotes int64 without x64 mode)
    const float* __restrict__ alpha,
    const float* __restrict__ im,
    float*       __restrict__ out)
{
    int p = blockIdx.x * blockDim.x + threadIdx.x;  // pixel within a batch image
    int b = blockIdx.y;
    size_t base = (size_t)b * K_ * HW_ + p;

    float T  = 1.f;
    float c0 = 0.f, c1 = 0.f, c2 = 0.f;
    bool  bg = false;

    #pragma unroll
    for (int half = 0; half < 2; half++) {
        // Batch-load 8 frags + 8 alphas (16 independent LDGs -> full MLP).
        int   f[8];
        float w[8];
        #pragma unroll
        for (int j = 0; j < 8; j++) {
            size_t off = base + (size_t)(half * 8 + j) * HW_;
            f[j] = frag[off];
            w[j] = alpha[off];
        }
        if (half == 0) {
            bg = (f[0] < 0);
            if (bg) T = 0.f;   // background: zero every weight -> zero gathers
        }

        // Weight chain in pure FMA; data-predicated truncation.
        #pragma unroll
        for (int j = 0; j < 8; j++) {
            bool  v  = (f[j] >= 0);
            float av = v ? w[j] : 0.f;
            w[j] = (v && T > EPS_T) ? av * T : 0.f;   // exclusive-transmittance weight
            T *= (1.f - av);
        }

        // Predicated independent gathers (skip all zero-weight layers).
        #pragma unroll
        for (int j = 0; j < 8; j++) {
            if (w[j] != 0.f) {
                float4 ft = __ldg(&g_tab[f[j]]);
                c0 = fmaf(w[j], ft.x, c0);
                c1 = fmaf(w[j], ft.y, c1);
                c2 = fmaf(w[j], ft.z, c2);
            }
        }
    }

    size_t ob = (size_t)b * 3 * HW_ + p;
    out[ob          ] = bg ? im[p          ] : c0;
    out[ob +     HW_] = bg ? im[p +     HW_] : c1;
    out[ob + 2 * HW_] = bg ? im[p + 2 * HW_] : c2;
}

extern "C" void kernel_launch(void* const* d_in, const int* in_sizes, int n_in,
                              void* d_out, int out_size) {
    const int*   frag  = (const int*)  d_in[0];
    const float* alpha = (const float*)d_in[1];
    const float* pt    = (const float*)d_in[2];
    const float* im    = (const float*)d_in[3];
    float*       out   = (float*)      d_out;

    prep_kernel<<<(P_ + 255) / 256, 256>>>(pt);

    dim3 grid(HW_ / 256, B_);   // 1200 x 4 blocks
    composite_kernel<<<grid, 256>>>(frag, alpha, im, out);
}

// round 12
// speedup vs baseline: 1.3975x; 1.0218x over previous
#include <cuda_runtime.h>

#define B_  4
#define K_  16
#define H_  480
#define W_  640
#define HW_ (H_*W_)
#define P_  200000

// Truncation threshold. Measured (R7/R8/R10): rel_err = 4.80e-4 (gate 1e-3).
#define EPS_T 1e-3f

// Pre-packed point-cloud features: one aligned 16B row per point -> one 32B
// L2 sector per gather.
__device__ float4 g_tab[P_];

__global__ void prep_kernel(const float* __restrict__ pt) {
    int i = blockIdx.x * blockDim.x + threadIdx.x;
    if (i < P_) {
        g_tab[i] = make_float4(pt[i], pt[P_ + i], pt[2 * P_ + i], 0.f);
    }
}

// R10 body unchanged; blocks shrunk 256->128 threads (16 blocks/SM, still a
// full 64 warps) to halve per-CTA duration -> less wave-drain/spread exposure.
__global__ void __launch_bounds__(128, 16) composite_kernel(
    const int*   __restrict__ frag,   // int32 (JAX demotes int64 without x64 mode)
    const float* __restrict__ alpha,
    const float* __restrict__ im,
    float*       __restrict__ out)
{
    int p = blockIdx.x * blockDim.x + threadIdx.x;  // pixel within a batch image
    int b = blockIdx.y;
    size_t base = (size_t)b * K_ * HW_ + p;

    float T  = 1.f;
    float c0 = 0.f, c1 = 0.f, c2 = 0.f;
    bool  bg = false;

    #pragma unroll
    for (int half = 0; half < 2; half++) {
        // Batch-load 8 frags + 8 alphas (16 independent LDGs -> full MLP).
        int   f[8];
        float w[8];
        #pragma unroll
        for (int j = 0; j < 8; j++) {
            size_t off = base + (size_t)(half * 8 + j) * HW_;
            f[j] = frag[off];
            w[j] = alpha[off];
        }
        if (half == 0) {
            bg = (f[0] < 0);
            if (bg) T = 0.f;   // background: zero every weight -> zero gathers
        }

        // Weight chain in pure FMA; data-predicated truncation.
        // (av is already 0 for invalid frags, so the T-test alone suffices.)
        #pragma unroll
        for (int j = 0; j < 8; j++) {
            float av = (f[j] >= 0) ? w[j] : 0.f;
            w[j] = (T > EPS_T) ? av * T : 0.f;   // exclusive-transmittance weight
            T *= (1.f - av);
        }

        // Predicated independent gathers (skip all zero-weight layers).
        #pragma unroll
        for (int j = 0; j < 8; j++) {
            if (w[j] != 0.f) {
                float4 ft = __ldg(&g_tab[f[j]]);
                c0 = fmaf(w[j], ft.x, c0);
                c1 = fmaf(w[j], ft.y, c1);
                c2 = fmaf(w[j], ft.z, c2);
            }
        }
    }

    size_t ob = (size_t)b * 3 * HW_ + p;
    out[ob          ] = bg ? im[p          ] : c0;
    out[ob +     HW_] = bg ? im[p +     HW_] : c1;
    out[ob + 2 * HW_] = bg ? im[p + 2 * HW_] : c2;
}

extern "C" void kernel_launch(void* const* d_in, const int* in_sizes, int n_in,
                              void* d_out, int out_size) {
    const int*   frag  = (const int*)  d_in[0];
    const float* alpha = (const float*)d_in[1];
    const float* pt    = (const float*)d_in[2];
    const float* im    = (const float*)d_in[3];
    float*       out   = (float*)      d_out;

    prep_kernel<<<(P_ + 255) / 256, 256>>>(pt);

    dim3 grid(HW_ / 128, B_);   // 2400 x 4 blocks, 128 pixels per block
    composite_kernel<<<grid, 128>>>(frag, alpha, im, out);
}